// round 1
// baseline (speedup 1.0000x reference)
#include <cuda_runtime.h>
#include <math.h>

#define D 2
#define E 16
#define H 1024
#define B 8192
#define K 2

#define TM 128
#define TN 128
#define TK 16
#define MAXT 160   // >= sum_e ceil(n_e/TM) <= B*K/TM + E = 144

// ---------------- device scratch (static globals: allowed) ----------------
static __device__ float g_x1[B * H];            // layer-0 output / layer-1 input
static __device__ float g_ysel[B * K * H];      // per-(token,slot) weighted expert output
static __device__ int   g_idx[B * K];           // selected expert per slot
static __device__ float g_wgt[B * K];           // softmax weight per slot
static __device__ int   g_counts[E];
static __device__ int   g_offs[E + 1];
static __device__ int   g_pos[E];
static __device__ int   g_perm[B * K];          // slot ids grouped by expert
static __device__ int   g_tile_e[MAXT];
static __device__ int   g_tile_row[MAXT];
static __device__ int   g_tile_rows[MAXT];
static __device__ int   g_ntiles;

// ---------------- gating: logits -> top2 -> softmax ----------------
// 512 threads = 16 warps (one per expert), 32 tokens per block.
__global__ void gate_kernel(const float* __restrict__ X,
                            const float* __restrict__ gw,
                            const float* __restrict__ gb, int d) {
    __shared__ float xs[H];
    __shared__ float logit_sm[E];
    const int warp = threadIdx.x >> 5;
    const int lane = threadIdx.x & 31;
    const float* xin = (d == 0) ? X : g_x1;

    // preload this warp's gate row into registers (32 floats/lane)
    float w[32];
    const float* gwr = gw + (size_t)(d * E + warp) * H;
#pragma unroll
    for (int j = 0; j < 32; j++) w[j] = gwr[lane + 32 * j];
    const float bias = gb[d * E + warp];

    const int tok0 = blockIdx.x * 32;
    for (int tt = 0; tt < 32; tt++) {
        const int b = tok0 + tt;
        ((float2*)xs)[threadIdx.x] = ((const float2*)(xin + (size_t)b * H))[threadIdx.x];
        __syncthreads();
        float s = 0.f;
#pragma unroll
        for (int j = 0; j < 32; j++) s += w[j] * xs[lane + 32 * j];
#pragma unroll
        for (int o = 16; o; o >>= 1) s += __shfl_xor_sync(0xffffffffu, s, o);
        if (lane == 0) logit_sm[warp] = s + bias;
        __syncthreads();
        if (threadIdx.x == 0) {
            float v1 = -INFINITY; int i1 = 0;
#pragma unroll
            for (int e = 0; e < E; e++)
                if (logit_sm[e] > v1) { v1 = logit_sm[e]; i1 = e; }
            float v2 = -INFINITY; int i2 = 0;
#pragma unroll
            for (int e = 0; e < E; e++)
                if (e != i1 && logit_sm[e] > v2) { v2 = logit_sm[e]; i2 = e; }
            const float e2 = __expf(v2 - v1);
            const float inv = 1.f / (1.f + e2);
            g_idx[b * K + 0] = i1;  g_wgt[b * K + 0] = inv;
            g_idx[b * K + 1] = i2;  g_wgt[b * K + 1] = e2 * inv;
        }
        __syncthreads();
    }
}

// ---------------- bucketing ----------------
__global__ void zero_counts_kernel() {
    if (threadIdx.x < E) g_counts[threadIdx.x] = 0;
}

__global__ void hist_kernel() {
    int i = blockIdx.x * blockDim.x + threadIdx.x;
    if (i < B * K) atomicAdd(&g_counts[g_idx[i]], 1);
}

// single-thread scan + tile-list build (trivial sizes)
__global__ void scan_tiles_kernel() {
    if (threadIdx.x != 0) return;
    int off = 0;
    for (int e = 0; e < E; e++) {
        g_offs[e] = off;
        g_pos[e]  = off;
        off += g_counts[e];
    }
    g_offs[E] = off;
    int nt = 0;
    for (int e = 0; e < E; e++) {
        const int n = g_counts[e];
        for (int r = 0; r < n; r += TM) {
            g_tile_e[nt]    = e;
            g_tile_row[nt]  = g_offs[e] + r;
            g_tile_rows[nt] = (n - r < TM) ? (n - r) : TM;
            nt++;
        }
    }
    g_ntiles = nt;
}

__global__ void scatter_kernel() {
    int i = blockIdx.x * blockDim.x + threadIdx.x;
    if (i < B * K) {
        int e = g_idx[i];
        int p = atomicAdd(&g_pos[e], 1);
        g_perm[p] = i;
    }
}

// ---------------- grouped expert GEMM + bias + PReLU + gate weight ----------------
// Tile: TM x TN x TK, 256 threads, 8x8 micro-tile per thread.
__global__ __launch_bounds__(256, 2)
void expert_gemm_kernel(const float* __restrict__ X,
                        const float* __restrict__ ew,
                        const float* __restrict__ eb,
                        const float* __restrict__ pl,
                        const float* __restrict__ pr,
                        const float* __restrict__ pp,
                        const float* __restrict__ pb, int d) {
    const int t = blockIdx.y;
    if (t >= g_ntiles) return;
    const int e    = g_tile_e[t];
    const int row0 = g_tile_row[t];
    const int rows = g_tile_rows[t];
    const int nb   = blockIdx.x * TN;

    __shared__ float As[TK][TM + 8];
    __shared__ float Bs[TK][TN + 8];
    __shared__ int   slots[TM];
    __shared__ int   toks[TM];

    const int tid = threadIdx.x;
    if (tid < TM) {
        if (tid < rows) {
            int s = g_perm[row0 + tid];
            slots[tid] = s;
            toks[tid]  = s >> 1;   // K == 2
        } else {
            slots[tid] = -1;
            toks[tid]  = -1;
        }
    }
    __syncthreads();

    const float* xin  = (d == 0) ? X : g_x1;
    const float* Wb   = ew + (size_t)(d * E + e) * H * H;

    float acc[8][8];
#pragma unroll
    for (int i = 0; i < 8; i++)
#pragma unroll
        for (int j = 0; j < 8; j++) acc[i][j] = 0.f;

    const int tx = tid & 15;
    const int ty = tid >> 4;

    for (int kb = 0; kb < H; kb += TK) {
        // load A (gathered token rows): 512 float4 slots, 2 per thread
#pragma unroll
        for (int i = 0; i < 2; i++) {
            int s  = tid + i * 256;
            int r  = s >> 2;
            int kq = (s & 3) * 4;
            float4 v = make_float4(0.f, 0.f, 0.f, 0.f);
            int tok = toks[r];
            if (tok >= 0) v = *(const float4*)(xin + (size_t)tok * H + kb + kq);
            As[kq + 0][r] = v.x; As[kq + 1][r] = v.y;
            As[kq + 2][r] = v.z; As[kq + 3][r] = v.w;
        }
        // load B (expert weight rows = output neurons)
#pragma unroll
        for (int i = 0; i < 2; i++) {
            int s  = tid + i * 256;
            int r  = s >> 2;
            int kq = (s & 3) * 4;
            float4 v = *(const float4*)(Wb + (size_t)(nb + r) * H + kb + kq);
            Bs[kq + 0][r] = v.x; Bs[kq + 1][r] = v.y;
            Bs[kq + 2][r] = v.z; Bs[kq + 3][r] = v.w;
        }
        __syncthreads();
#pragma unroll
        for (int k = 0; k < TK; k++) {
            float a[8], b[8];
            *(float4*)(a)     = *(const float4*)&As[k][ty * 8];
            *(float4*)(a + 4) = *(const float4*)&As[k][ty * 8 + 4];
            *(float4*)(b)     = *(const float4*)&Bs[k][tx * 8];
            *(float4*)(b + 4) = *(const float4*)&Bs[k][tx * 8 + 4];
#pragma unroll
            for (int i = 0; i < 8; i++)
#pragma unroll
                for (int j = 0; j < 8; j++) acc[i][j] += a[i] * b[j];
        }
        __syncthreads();
    }

    // epilogue: bias + PReLU + gate weight, write to per-slot buffer
    const int de = d * E + e;
    const float* ebr = eb + (size_t)de * H + nb;
    const float* plr = pl + (size_t)de * H + nb;
    const float* prr = pr + (size_t)de * H + nb;
    const float* ppr = pp + (size_t)de * H + nb;
    const float* pbr = pb + (size_t)de * H + nb;
#pragma unroll
    for (int i = 0; i < 8; i++) {
        const int r = ty * 8 + i;
        const int slot = slots[r];
        if (slot < 0) continue;
        const float w = g_wgt[slot];
        float* orow = g_ysel + (size_t)slot * H + nb;
#pragma unroll
        for (int j = 0; j < 8; j++) {
            const int c = tx * 8 + j;
            float y   = acc[i][j] + ebr[c];
            float dl  = y - ppr[c];
            float act = pbr[c] + (dl >= 0.f ? dl * prr[c] : dl * plr[c]);
            orow[c] = act * w;
        }
    }
}

// ---------------- combine the K=2 weighted slots ----------------
__global__ void combine_kernel(float* __restrict__ out, int d) {
    const int i = blockIdx.x * blockDim.x + threadIdx.x;   // over B*H/4
    const int HQ = H / 4;
    const int b  = i / HQ;
    const int h4 = i - b * HQ;
    const float4* y = (const float4*)g_ysel;
    float4 a = y[(size_t)(2 * b) * HQ + h4];
    float4 c = y[(size_t)(2 * b + 1) * HQ + h4];
    float4 r = make_float4(a.x + c.x, a.y + c.y, a.z + c.z, a.w + c.w);
    float* dst = (d == 0) ? g_x1 : out;
    ((float4*)dst)[i] = r;
}

// ---------------- launch ----------------
extern "C" void kernel_launch(void* const* d_in, const int* in_sizes, int n_in,
                              void* d_out, int out_size) {
    const float* X  = (const float*)d_in[0];
    const float* gw = (const float*)d_in[1];
    const float* gb = (const float*)d_in[2];
    const float* ew = (const float*)d_in[3];
    const float* eb = (const float*)d_in[4];
    const float* pl = (const float*)d_in[5];
    const float* pr = (const float*)d_in[6];
    const float* pp = (const float*)d_in[7];
    const float* pb = (const float*)d_in[8];
    float* out = (float*)d_out;

    for (int d = 0; d < D; d++) {
        gate_kernel<<<B / 32, 512>>>(X, gw, gb, d);
        zero_counts_kernel<<<1, 32>>>();
        hist_kernel<<<(B * K + 255) / 256, 256>>>();
        scan_tiles_kernel<<<1, 32>>>();
        scatter_kernel<<<(B * K + 255) / 256, 256>>>();
        expert_gemm_kernel<<<dim3(H / TN, MAXT), 256>>>(X, ew, eb, pl, pr, pp, pb, d);
        combine_kernel<<<(B * H / 4 + 255) / 256, 256>>>(out, d);
    }
}

// round 2
// speedup vs baseline: 1.0011x; 1.0011x over previous
#include <cuda_runtime.h>
#include <math.h>

#define D 2
#define E 16
#define H 1024
#define B 8192
#define K 2

#define TM 128
#define TN 128
#define TK 16
#define MAXT 160   // >= sum_e ceil(n_e/TM) <= B*K/TM + E = 144

// ---------------- device scratch (static globals: allowed) ----------------
static __device__ float g_x1[B * H];            // layer-0 output / layer-1 input
static __device__ float g_ysel[B * K * H];      // per-(token,slot) weighted expert output
static __device__ int   g_idx[B * K];           // selected expert per slot
static __device__ float g_wgt[B * K];           // softmax weight per slot
static __device__ int   g_counts[E];
static __device__ int   g_offs[E + 1];
static __device__ int   g_pos[E];
static __device__ int   g_perm[B * K];          // slot ids grouped by expert
static __device__ int   g_tile_e[MAXT];
static __device__ int   g_tile_row[MAXT];
static __device__ int   g_tile_rows[MAXT];
static __device__ int   g_ntiles;

// ---------------- gating: logits -> top2 -> softmax ----------------
// 512 threads = 16 warps (one per expert), 32 tokens per block.
__global__ void gate_kernel(const float* __restrict__ X,
                            const float* __restrict__ gw,
                            const float* __restrict__ gb, int d) {
    __shared__ float xs[H];
    __shared__ float logit_sm[E];
    const int warp = threadIdx.x >> 5;
    const int lane = threadIdx.x & 31;
    const float* xin = (d == 0) ? X : g_x1;

    // preload this warp's gate row into registers (32 floats/lane)
    float w[32];
    const float* gwr = gw + (size_t)(d * E + warp) * H;
#pragma unroll
    for (int j = 0; j < 32; j++) w[j] = gwr[lane + 32 * j];
    const float bias = gb[d * E + warp];

    const int tok0 = blockIdx.x * 32;
    for (int tt = 0; tt < 32; tt++) {
        const int b = tok0 + tt;
        ((float2*)xs)[threadIdx.x] = ((const float2*)(xin + (size_t)b * H))[threadIdx.x];
        __syncthreads();
        float s = 0.f;
#pragma unroll
        for (int j = 0; j < 32; j++) s += w[j] * xs[lane + 32 * j];
#pragma unroll
        for (int o = 16; o; o >>= 1) s += __shfl_xor_sync(0xffffffffu, s, o);
        if (lane == 0) logit_sm[warp] = s + bias;
        __syncthreads();
        if (threadIdx.x == 0) {
            float v1 = -INFINITY; int i1 = 0;
#pragma unroll
            for (int e = 0; e < E; e++)
                if (logit_sm[e] > v1) { v1 = logit_sm[e]; i1 = e; }
            float v2 = -INFINITY; int i2 = 0;
#pragma unroll
            for (int e = 0; e < E; e++)
                if (e != i1 && logit_sm[e] > v2) { v2 = logit_sm[e]; i2 = e; }
            const float e2 = __expf(v2 - v1);
            const float inv = 1.f / (1.f + e2);
            g_idx[b * K + 0] = i1;  g_wgt[b * K + 0] = inv;
            g_idx[b * K + 1] = i2;  g_wgt[b * K + 1] = e2 * inv;
        }
        __syncthreads();
    }
}

// ---------------- bucketing ----------------
__global__ void zero_counts_kernel() {
    if (threadIdx.x < E) g_counts[threadIdx.x] = 0;
}

__global__ void hist_kernel() {
    int i = blockIdx.x * blockDim.x + threadIdx.x;
    if (i < B * K) atomicAdd(&g_counts[g_idx[i]], 1);
}

// single-thread scan + tile-list build (trivial sizes)
__global__ void scan_tiles_kernel() {
    if (threadIdx.x != 0) return;
    int off = 0;
    for (int e = 0; e < E; e++) {
        g_offs[e] = off;
        g_pos[e]  = off;
        off += g_counts[e];
    }
    g_offs[E] = off;
    int nt = 0;
    for (int e = 0; e < E; e++) {
        const int n = g_counts[e];
        for (int r = 0; r < n; r += TM) {
            g_tile_e[nt]    = e;
            g_tile_row[nt]  = g_offs[e] + r;
            g_tile_rows[nt] = (n - r < TM) ? (n - r) : TM;
            nt++;
        }
    }
    g_ntiles = nt;
}

__global__ void scatter_kernel() {
    int i = blockIdx.x * blockDim.x + threadIdx.x;
    if (i < B * K) {
        int e = g_idx[i];
        int p = atomicAdd(&g_pos[e], 1);
        g_perm[p] = i;
    }
}

// ---------------- grouped expert GEMM + bias + PReLU + gate weight ----------------
// Tile: TM x TN x TK, 256 threads, 8x8 micro-tile per thread.
__global__ __launch_bounds__(256, 2)
void expert_gemm_kernel(const float* __restrict__ X,
                        const float* __restrict__ ew,
                        const float* __restrict__ eb,
                        const float* __restrict__ pl,
                        const float* __restrict__ pr,
                        const float* __restrict__ pp,
                        const float* __restrict__ pb, int d) {
    const int t = blockIdx.y;
    if (t >= g_ntiles) return;
    const int e    = g_tile_e[t];
    const int row0 = g_tile_row[t];
    const int rows = g_tile_rows[t];
    const int nb   = blockIdx.x * TN;

    __shared__ float As[TK][TM + 8];
    __shared__ float Bs[TK][TN + 8];
    __shared__ int   slots[TM];
    __shared__ int   toks[TM];

    const int tid = threadIdx.x;
    if (tid < TM) {
        if (tid < rows) {
            int s = g_perm[row0 + tid];
            slots[tid] = s;
            toks[tid]  = s >> 1;   // K == 2
        } else {
            slots[tid] = -1;
            toks[tid]  = -1;
        }
    }
    __syncthreads();

    const float* xin  = (d == 0) ? X : g_x1;
    const float* Wb   = ew + (size_t)(d * E + e) * H * H;

    float acc[8][8];
#pragma unroll
    for (int i = 0; i < 8; i++)
#pragma unroll
        for (int j = 0; j < 8; j++) acc[i][j] = 0.f;

    const int tx = tid & 15;
    const int ty = tid >> 4;

    for (int kb = 0; kb < H; kb += TK) {
        // load A (gathered token rows): 512 float4 slots, 2 per thread
#pragma unroll
        for (int i = 0; i < 2; i++) {
            int s  = tid + i * 256;
            int r  = s >> 2;
            int kq = (s & 3) * 4;
            float4 v = make_float4(0.f, 0.f, 0.f, 0.f);
            int tok = toks[r];
            if (tok >= 0) v = *(const float4*)(xin + (size_t)tok * H + kb + kq);
            As[kq + 0][r] = v.x; As[kq + 1][r] = v.y;
            As[kq + 2][r] = v.z; As[kq + 3][r] = v.w;
        }
        // load B (expert weight rows = output neurons)
#pragma unroll
        for (int i = 0; i < 2; i++) {
            int s  = tid + i * 256;
            int r  = s >> 2;
            int kq = (s & 3) * 4;
            float4 v = *(const float4*)(Wb + (size_t)(nb + r) * H + kb + kq);
            Bs[kq + 0][r] = v.x; Bs[kq + 1][r] = v.y;
            Bs[kq + 2][r] = v.z; Bs[kq + 3][r] = v.w;
        }
        __syncthreads();
#pragma unroll
        for (int k = 0; k < TK; k++) {
            float a[8], b[8];
            *(float4*)(a)     = *(const float4*)&As[k][ty * 8];
            *(float4*)(a + 4) = *(const float4*)&As[k][ty * 8 + 4];
            *(float4*)(b)     = *(const float4*)&Bs[k][tx * 8];
            *(float4*)(b + 4) = *(const float4*)&Bs[k][tx * 8 + 4];
#pragma unroll
            for (int i = 0; i < 8; i++)
#pragma unroll
                for (int j = 0; j < 8; j++) acc[i][j] += a[i] * b[j];
        }
        __syncthreads();
    }

    // epilogue: bias + PReLU + gate weight, write to per-slot buffer
    const int de = d * E + e;
    const float* ebr = eb + (size_t)de * H + nb;
    const float* plr = pl + (size_t)de * H + nb;
    const float* prr = pr + (size_t)de * H + nb;
    const float* ppr = pp + (size_t)de * H + nb;
    const float* pbr = pb + (size_t)de * H + nb;
#pragma unroll
    for (int i = 0; i < 8; i++) {
        const int r = ty * 8 + i;
        const int slot = slots[r];
        if (slot < 0) continue;
        const float w = g_wgt[slot];
        float* orow = g_ysel + (size_t)slot * H + nb;
#pragma unroll
        for (int j = 0; j < 8; j++) {
            const int c = tx * 8 + j;
            float y   = acc[i][j] + ebr[c];
            float dl  = y - ppr[c];
            float act = pbr[c] + (dl >= 0.f ? dl * prr[c] : dl * plr[c]);
            orow[c] = act * w;
        }
    }
}

// ---------------- combine the K=2 weighted slots ----------------
__global__ void combine_kernel(float* __restrict__ out, int d) {
    const int i = blockIdx.x * blockDim.x + threadIdx.x;   // over B*H/4
    const int HQ = H / 4;
    const int b  = i / HQ;
    const int h4 = i - b * HQ;
    const float4* y = (const float4*)g_ysel;
    float4 a = y[(size_t)(2 * b) * HQ + h4];
    float4 c = y[(size_t)(2 * b + 1) * HQ + h4];
    float4 r = make_float4(a.x + c.x, a.y + c.y, a.z + c.z, a.w + c.w);
    float* dst = (d == 0) ? g_x1 : out;
    ((float4*)dst)[i] = r;
}

// ---------------- launch ----------------
extern "C" void kernel_launch(void* const* d_in, const int* in_sizes, int n_in,
                              void* d_out, int out_size) {
    const float* X  = (const float*)d_in[0];
    const float* gw = (const float*)d_in[1];
    const float* gb = (const float*)d_in[2];
    const float* ew = (const float*)d_in[3];
    const float* eb = (const float*)d_in[4];
    const float* pl = (const float*)d_in[5];
    const float* pr = (const float*)d_in[6];
    const float* pp = (const float*)d_in[7];
    const float* pb = (const float*)d_in[8];
    float* out = (float*)d_out;

    for (int d = 0; d < D; d++) {
        gate_kernel<<<B / 32, 512>>>(X, gw, gb, d);
        zero_counts_kernel<<<1, 32>>>();
        hist_kernel<<<(B * K + 255) / 256, 256>>>();
        scan_tiles_kernel<<<1, 32>>>();
        scatter_kernel<<<(B * K + 255) / 256, 256>>>();
        expert_gemm_kernel<<<dim3(H / TN, MAXT), 256>>>(X, ew, eb, pl, pr, pp, pb, d);
        combine_kernel<<<(B * H / 4 + 255) / 256, 256>>>(out, d);
    }
}

// round 7
// speedup vs baseline: 2.1792x; 2.1768x over previous
#include <cuda_runtime.h>
#include <cuda_bf16.h>
#include <math.h>
#include <stdint.h>

#define D 2
#define E 16
#define H 1024
#define B 8192
#define K 2

#define TM 128
#define TN 128
#define TKB 32                 // k elements per stage
#define NC (H / TKB)           // 32 stages
#define MAXT 160

#define ROWB 80                          // 32 bf16 = 64B + 16B pad (stride 5 chunks, gcd(5,8)=1)
#define TILE_B (TM * ROWB)               // 10240
#define STAGE_B (4 * TILE_B)             // Ah, Al, Bh, Bl = 40960
#define DYN_SMEM (2 * STAGE_B)           // 81920

// ---------------- device scratch ----------------
static __device__ float g_x1[B * H];
static __device__ float g_ysel[B * K * H];
static __device__ int   g_idx[B * K];
static __device__ float g_wgt[B * K];
static __device__ int   g_counts[E];
static __device__ int   g_offs[E + 1];
static __device__ int   g_pos[E];
static __device__ int   g_perm[B * K];
static __device__ int   g_tile_e[MAXT];
static __device__ int   g_tile_row[MAXT];
static __device__ int   g_tile_rows[MAXT];
static __device__ int   g_ntiles;
// bf16 hi/lo copies
static __device__ __nv_bfloat16 g_wh[(size_t)D * E * H * H];
static __device__ __nv_bfloat16 g_wl[(size_t)D * E * H * H];
static __device__ __nv_bfloat16 g_xh[B * H];
static __device__ __nv_bfloat16 g_xl[B * H];

// ---------------- PTX helpers (sm_80-level, OK on base sm_103 target) ----------------
__device__ __forceinline__ uint32_t smem_u32(const void* p) {
    uint32_t a;
    asm("{ .reg .u64 t; cvta.to.shared.u64 t, %1; cvt.u32.u64 %0, t; }" : "=r"(a) : "l"(p));
    return a;
}

__device__ __forceinline__ void cpasync16(uint32_t dst, const void* src, int src_sz) {
    asm volatile("cp.async.cg.shared.global [%0], [%1], 16, %2;"
                 :: "r"(dst), "l"(src), "r"(src_sz) : "memory");
}

__device__ __forceinline__ void ldsm4(uint32_t* r, uint32_t addr) {
    asm volatile("ldmatrix.sync.aligned.m8n8.x4.shared.b16 {%0,%1,%2,%3}, [%4];"
                 : "=r"(r[0]), "=r"(r[1]), "=r"(r[2]), "=r"(r[3]) : "r"(addr));
}

__device__ __forceinline__ void ldsm2(uint32_t* r, uint32_t addr) {
    asm volatile("ldmatrix.sync.aligned.m8n8.x2.shared.b16 {%0,%1}, [%2];"
                 : "=r"(r[0]), "=r"(r[1]) : "r"(addr));
}

__device__ __forceinline__ void mma16816(float* c, const uint32_t* a, const uint32_t* b) {
    asm volatile(
        "mma.sync.aligned.m16n8k16.row.col.f32.bf16.bf16.f32 "
        "{%0,%1,%2,%3}, {%4,%5,%6,%7}, {%8,%9}, {%0,%1,%2,%3};"
        : "+f"(c[0]), "+f"(c[1]), "+f"(c[2]), "+f"(c[3])
        : "r"(a[0]), "r"(a[1]), "r"(a[2]), "r"(a[3]), "r"(b[0]), "r"(b[1]));
}

// ---------------- hi/lo bf16 split converters ----------------
__global__ void convert_w_kernel(const float* __restrict__ ew) {
    const size_t i = (size_t)blockIdx.x * blockDim.x + threadIdx.x;   // float4 index
    const float4 v = ((const float4*)ew)[i];
    __nv_bfloat16 h[4]; float f[4] = {v.x, v.y, v.z, v.w};
    __nv_bfloat16 l[4];
#pragma unroll
    for (int j = 0; j < 4; j++) {
        h[j] = __float2bfloat16(f[j]);
        l[j] = __float2bfloat16(f[j] - __bfloat162float(h[j]));
    }
    *(uint2*)&g_wh[i * 4] = *(uint2*)h;
    *(uint2*)&g_wl[i * 4] = *(uint2*)l;
}

__global__ void convert_x_kernel(const float* __restrict__ X, int d) {
    const float* xin = (d == 0) ? X : g_x1;
    const size_t i = (size_t)blockIdx.x * blockDim.x + threadIdx.x;
    const float4 v = ((const float4*)xin)[i];
    __nv_bfloat16 h[4]; float f[4] = {v.x, v.y, v.z, v.w};
    __nv_bfloat16 l[4];
#pragma unroll
    for (int j = 0; j < 4; j++) {
        h[j] = __float2bfloat16(f[j]);
        l[j] = __float2bfloat16(f[j] - __bfloat162float(h[j]));
    }
    *(uint2*)&g_xh[i * 4] = *(uint2*)h;
    *(uint2*)&g_xl[i * 4] = *(uint2*)l;
}

// ---------------- gating: logits -> top2 -> softmax (fp32, exact) ----------------
__global__ void gate_kernel(const float* __restrict__ X,
                            const float* __restrict__ gw,
                            const float* __restrict__ gb, int d) {
    __shared__ float xs[H];
    __shared__ float logit_sm[E];
    const int warp = threadIdx.x >> 5;
    const int lane = threadIdx.x & 31;
    const float* xin = (d == 0) ? X : g_x1;

    float w[32];
    const float* gwr = gw + (size_t)(d * E + warp) * H;
#pragma unroll
    for (int j = 0; j < 32; j++) w[j] = gwr[lane + 32 * j];
    const float bias = gb[d * E + warp];

    const int tok0 = blockIdx.x * 32;
    for (int tt = 0; tt < 32; tt++) {
        const int b = tok0 + tt;
        ((float2*)xs)[threadIdx.x] = ((const float2*)(xin + (size_t)b * H))[threadIdx.x];
        __syncthreads();
        float s = 0.f;
#pragma unroll
        for (int j = 0; j < 32; j++) s += w[j] * xs[lane + 32 * j];
#pragma unroll
        for (int o = 16; o; o >>= 1) s += __shfl_xor_sync(0xffffffffu, s, o);
        if (lane == 0) logit_sm[warp] = s + bias;
        __syncthreads();
        if (threadIdx.x == 0) {
            float v1 = -INFINITY; int i1 = 0;
#pragma unroll
            for (int e = 0; e < E; e++)
                if (logit_sm[e] > v1) { v1 = logit_sm[e]; i1 = e; }
            float v2 = -INFINITY; int i2 = 0;
#pragma unroll
            for (int e = 0; e < E; e++)
                if (e != i1 && logit_sm[e] > v2) { v2 = logit_sm[e]; i2 = e; }
            const float e2 = __expf(v2 - v1);
            const float inv = 1.f / (1.f + e2);
            g_idx[b * K + 0] = i1;  g_wgt[b * K + 0] = inv;
            g_idx[b * K + 1] = i2;  g_wgt[b * K + 1] = e2 * inv;
        }
        __syncthreads();
    }
}

// ---------------- bucketing ----------------
__global__ void zero_counts_kernel() {
    if (threadIdx.x < E) g_counts[threadIdx.x] = 0;
}

__global__ void hist_kernel() {
    int i = blockIdx.x * blockDim.x + threadIdx.x;
    if (i < B * K) atomicAdd(&g_counts[g_idx[i]], 1);
}

__global__ void scan_tiles_kernel() {
    if (threadIdx.x != 0) return;
    int off = 0;
    for (int e = 0; e < E; e++) {
        g_offs[e] = off;
        g_pos[e]  = off;
        off += g_counts[e];
    }
    g_offs[E] = off;
    int nt = 0;
    for (int e = 0; e < E; e++) {
        const int n = g_counts[e];
        for (int r = 0; r < n; r += TM) {
            g_tile_e[nt]    = e;
            g_tile_row[nt]  = g_offs[e] + r;
            g_tile_rows[nt] = (n - r < TM) ? (n - r) : TM;
            nt++;
        }
    }
    g_ntiles = nt;
}

__global__ void scatter_kernel() {
    int i = blockIdx.x * blockDim.x + threadIdx.x;
    if (i < B * K) {
        int e = g_idx[i];
        int p = atomicAdd(&g_pos[e], 1);
        g_perm[p] = i;
    }
}

// ---------------- bf16x3 mma.sync grouped GEMM + fused epilogue ----------------
// 128x128 C tile, 8 warps in 2(m) x 4(n), warp tile 64x32, mma m16n8k16.
__global__ __launch_bounds__(256, 1)
void expert_gemm_mma(const float* __restrict__ eb,
                     const float* __restrict__ pl,
                     const float* __restrict__ pr,
                     const float* __restrict__ pp,
                     const float* __restrict__ pb, int d)
{
    const int t = blockIdx.y;
    if (t >= g_ntiles) return;
    const int e    = g_tile_e[t];
    const int row0 = g_tile_row[t];
    const int rows = g_tile_rows[t];
    const int nb   = blockIdx.x * TN;
    const int de   = d * E + e;

    extern __shared__ char dsm[];
    const uint32_t sb = smem_u32(dsm);

    __shared__ int   toks_sm[TM];
    __shared__ int   slots_sm[TM];
    __shared__ float wgt_sm[TM];
    __shared__ float prm[5][TN];

    const int tid  = threadIdx.x;
    const int wid  = tid >> 5;
    const int lane = tid & 31;

    if (tid < TM) {
        int s = (tid < rows) ? g_perm[row0 + tid] : -1;
        slots_sm[tid] = s;
        toks_sm[tid]  = (s >= 0) ? (s >> 1) : -1;
        wgt_sm[tid]   = (s >= 0) ? g_wgt[s] : 0.f;
    }
    if (tid < TN) {
        const size_t pofs = (size_t)de * H + nb + tid;
        prm[0][tid] = eb[pofs];
        prm[1][tid] = pl[pofs];
        prm[2][tid] = pr[pofs];
        prm[3][tid] = pp[pofs];
        prm[4][tid] = pb[pofs];
    }
    __syncthreads();

    // loader geometry: q in [0,512): r=q>>2 (row), c=q&3 (16B chunk); this thread q=tid, tid+256
    const int r0l = tid >> 2,        c0l = tid & 3;
    const int r1l = (tid + 256) >> 2, c1l = c0l;
    const int tk0 = toks_sm[r0l], tk1 = toks_sm[r1l];
    const __nv_bfloat16* Wh = g_wh + (size_t)de * H * H;
    const __nv_bfloat16* Wl = g_wl + (size_t)de * H * H;

#define ISSUE_STAGE(i)                                                                   \
    do {                                                                                 \
        const int kb_ = (i) * TKB;                                                       \
        const uint32_t st_ = sb + ((i) & 1) * STAGE_B;                                   \
        /* A hi/lo */                                                                    \
        {                                                                                \
            const uint32_t o0 = st_ + r0l * ROWB + c0l * 16;                             \
            const uint32_t o1 = st_ + r1l * ROWB + c1l * 16;                             \
            const size_t g0 = (size_t)(tk0 < 0 ? 0 : tk0) * H + kb_ + c0l * 8;           \
            const size_t g1 = (size_t)(tk1 < 0 ? 0 : tk1) * H + kb_ + c1l * 8;           \
            cpasync16(o0,              g_xh + g0, tk0 < 0 ? 0 : 16);                     \
            cpasync16(o1,              g_xh + g1, tk1 < 0 ? 0 : 16);                     \
            cpasync16(o0 + TILE_B,     g_xl + g0, tk0 < 0 ? 0 : 16);                     \
            cpasync16(o1 + TILE_B,     g_xl + g1, tk1 < 0 ? 0 : 16);                     \
        }                                                                                \
        /* B hi/lo */                                                                    \
        {                                                                                \
            const uint32_t o0 = st_ + 2 * TILE_B + r0l * ROWB + c0l * 16;                \
            const uint32_t o1 = st_ + 2 * TILE_B + r1l * ROWB + c1l * 16;                \
            const size_t g0 = (size_t)(nb + r0l) * H + kb_ + c0l * 8;                    \
            const size_t g1 = (size_t)(nb + r1l) * H + kb_ + c1l * 8;                    \
            cpasync16(o0,              Wh + g0, 16);                                     \
            cpasync16(o1,              Wh + g1, 16);                                     \
            cpasync16(o0 + TILE_B,     Wl + g0, 16);                                     \
            cpasync16(o1 + TILE_B,     Wl + g1, 16);                                     \
        }                                                                                \
        asm volatile("cp.async.commit_group;" ::: "memory");                             \
    } while (0)

    float acc[4][4][4];
#pragma unroll
    for (int mi = 0; mi < 4; mi++)
#pragma unroll
        for (int ni = 0; ni < 4; ni++)
#pragma unroll
            for (int u = 0; u < 4; u++) acc[mi][ni][u] = 0.f;

    const int warp_m = wid & 1, warp_n = wid >> 1;
    const int m0 = warp_m * 64, n0 = warp_n * 32;

    // per-thread ldmatrix base offsets (within a tile)
    const uint32_t a_off = (uint32_t)((m0 + (lane & 15)) * ROWB + (lane >> 4) * 16);
    const uint32_t b_off = (uint32_t)((n0 + (lane & 7)) * ROWB + ((lane >> 3) & 1) * 16);

    ISSUE_STAGE(0);
    ISSUE_STAGE(1);

    for (int i = 0; i < NC; i++) {
        if (i + 1 < NC) asm volatile("cp.async.wait_group 1;" ::: "memory");
        else            asm volatile("cp.async.wait_group 0;" ::: "memory");
        __syncthreads();

        const uint32_t st = sb + (i & 1) * STAGE_B;
        const uint32_t Ah = st + a_off;
        const uint32_t Al = Ah + TILE_B;
        const uint32_t Bh = st + 2 * TILE_B + b_off;
        const uint32_t Bl = Bh + TILE_B;

#pragma unroll
        for (int ks = 0; ks < 2; ks++) {
            uint32_t ah[4][4], al[4][4], bh[4][2], bl[4][2];
#pragma unroll
            for (int mi = 0; mi < 4; mi++) {
                ldsm4(ah[mi], Ah + mi * (16 * ROWB) + ks * 32);
                ldsm4(al[mi], Al + mi * (16 * ROWB) + ks * 32);
            }
#pragma unroll
            for (int ni = 0; ni < 4; ni++) {
                ldsm2(bh[ni], Bh + ni * (8 * ROWB) + ks * 32);
                ldsm2(bl[ni], Bl + ni * (8 * ROWB) + ks * 32);
            }
#pragma unroll
            for (int mi = 0; mi < 4; mi++)
#pragma unroll
                for (int ni = 0; ni < 4; ni++) {
                    mma16816(acc[mi][ni], ah[mi], bh[ni]);
                    mma16816(acc[mi][ni], ah[mi], bl[ni]);
                    mma16816(acc[mi][ni], al[mi], bh[ni]);
                }
        }
        __syncthreads();
        if (i + 2 < NC) ISSUE_STAGE(i + 2);
    }

    // ---------------- epilogue: bias + PReLU + gate weight ----------------
#pragma unroll
    for (int mi = 0; mi < 4; mi++) {
        const int ra = m0 + mi * 16 + (lane >> 2);
        const int rb2 = ra + 8;
        const int sa = slots_sm[ra], sbt = slots_sm[rb2];
        const float wa = wgt_sm[ra], wb = wgt_sm[rb2];
#pragma unroll
        for (int ni = 0; ni < 4; ni++) {
            const int c = n0 + ni * 8 + (lane & 3) * 2;   // nb-relative, even
            const float* pe = &prm[0][c];
            if (sa >= 0) {
                float2 o;
                float y0 = acc[mi][ni][0] + prm[0][c];
                float y1 = acc[mi][ni][1] + prm[0][c + 1];
                float d0 = y0 - prm[3][c],     d1 = y1 - prm[3][c + 1];
                o.x = (prm[4][c]   + (d0 >= 0.f ? d0 * prm[2][c]   : d0 * prm[1][c]))   * wa;
                o.y = (prm[4][c+1] + (d1 >= 0.f ? d1 * prm[2][c+1] : d1 * prm[1][c+1])) * wa;
                *(float2*)(g_ysel + (size_t)sa * H + nb + c) = o;
            }
            if (sbt >= 0) {
                float2 o;
                float y0 = acc[mi][ni][2] + prm[0][c];
                float y1 = acc[mi][ni][3] + prm[0][c + 1];
                float d0 = y0 - prm[3][c],     d1 = y1 - prm[3][c + 1];
                o.x = (prm[4][c]   + (d0 >= 0.f ? d0 * prm[2][c]   : d0 * prm[1][c]))   * wb;
                o.y = (prm[4][c+1] + (d1 >= 0.f ? d1 * prm[2][c+1] : d1 * prm[1][c+1])) * wb;
                *(float2*)(g_ysel + (size_t)sbt * H + nb + c) = o;
            }
            (void)pe;
        }
    }
#undef ISSUE_STAGE
}

// ---------------- combine the K=2 weighted slots ----------------
__global__ void combine_kernel(float* __restrict__ out, int d) {
    const int i = blockIdx.x * blockDim.x + threadIdx.x;   // over B*H/4
    const int HQ = H / 4;
    const int b  = i / HQ;
    const int h4 = i - b * HQ;
    const float4* y = (const float4*)g_ysel;
    float4 a = y[(size_t)(2 * b) * HQ + h4];
    float4 c = y[(size_t)(2 * b + 1) * HQ + h4];
    float4 r = make_float4(a.x + c.x, a.y + c.y, a.z + c.z, a.w + c.w);
    float* dst = (d == 0) ? g_x1 : out;
    ((float4*)dst)[i] = r;
}

// ---------------- launch ----------------
extern "C" void kernel_launch(void* const* d_in, const int* in_sizes, int n_in,
                              void* d_out, int out_size) {
    const float* X  = (const float*)d_in[0];
    const float* gw = (const float*)d_in[1];
    const float* gb = (const float*)d_in[2];
    const float* ew = (const float*)d_in[3];
    const float* eb = (const float*)d_in[4];
    const float* pl = (const float*)d_in[5];
    const float* pr = (const float*)d_in[6];
    const float* pp = (const float*)d_in[7];
    const float* pb = (const float*)d_in[8];
    float* out = (float*)d_out;

    static bool attr_done = false;
    if (!attr_done) {
        cudaFuncSetAttribute(expert_gemm_mma,
                             cudaFuncAttributeMaxDynamicSharedMemorySize, DYN_SMEM);
        attr_done = true;
    }

    // weights -> bf16 hi/lo (once per launch)
    convert_w_kernel<<<(size_t)D * E * H * H / 4 / 256, 256>>>(ew);

    for (int d = 0; d < D; d++) {
        gate_kernel<<<B / 32, 512>>>(X, gw, gb, d);
        convert_x_kernel<<<B * H / 4 / 256, 256>>>(X, d);
        zero_counts_kernel<<<1, 32>>>();
        hist_kernel<<<(B * K + 255) / 256, 256>>>();
        scan_tiles_kernel<<<1, 32>>>();
        scatter_kernel<<<(B * K + 255) / 256, 256>>>();
        expert_gemm_mma<<<dim3(H / TN, MAXT), 256, DYN_SMEM>>>(eb, pl, pr, pp, pb, d);
        combine_kernel<<<(B * H / 4 + 255) / 256, 256>>>(out, d);
    }
}

// round 9
// speedup vs baseline: 2.4647x; 1.1310x over previous
#include <cuda_runtime.h>
#include <cuda_fp16.h>
#include <math.h>
#include <stdint.h>

#define D 2
#define E 16
#define H 1024
#define B 8192
#define K 2

#define TM 128
#define TN 128
#define TKB 32                 // k elements per stage
#define NC (H / TKB)           // 32 stages
#define MAXT 160

#define ROWB 80                          // 32 fp16 = 64B + 16B pad (stride 5 chunks, gcd(5,8)=1)
#define TILE_B (TM * ROWB)               // 10240
#define STAGE_B (4 * TILE_B)             // Ah, Al, Bh, Bl = 40960
#define DYN_SMEM (2 * STAGE_B)           // 81920

// ---------------- device scratch ----------------
static __device__ float g_x1[B * H];
static __device__ float g_ysel[B * K * H];
static __device__ int   g_idx[B * K];
static __device__ float g_wgt[B * K];
static __device__ int   g_counts[E];
static __device__ int   g_offs[E + 1];
static __device__ int   g_pos[E];
static __device__ int   g_perm[B * K];
static __device__ int   g_tile_e[MAXT];
static __device__ int   g_tile_row[MAXT];
static __device__ int   g_tile_rows[MAXT];
static __device__ int   g_ntiles;
// fp16 hi/lo copies (W lo needed for layer 0 only)
static __device__ __half g_wh[(size_t)D * E * H * H];
static __device__ __half g_wl[(size_t)E * H * H];
static __device__ __half g_xh[B * H];
static __device__ __half g_xl[B * H];

// ---------------- PTX helpers ----------------
__device__ __forceinline__ uint32_t smem_u32(const void* p) {
    uint32_t a;
    asm("{ .reg .u64 t; cvta.to.shared.u64 t, %1; cvt.u32.u64 %0, t; }" : "=r"(a) : "l"(p));
    return a;
}

__device__ __forceinline__ void cpasync16(uint32_t dst, const void* src, int src_sz) {
    asm volatile("cp.async.cg.shared.global [%0], [%1], 16, %2;"
                 :: "r"(dst), "l"(src), "r"(src_sz) : "memory");
}

__device__ __forceinline__ void ldsm4(uint32_t* r, uint32_t addr) {
    asm volatile("ldmatrix.sync.aligned.m8n8.x4.shared.b16 {%0,%1,%2,%3}, [%4];"
                 : "=r"(r[0]), "=r"(r[1]), "=r"(r[2]), "=r"(r[3]) : "r"(addr));
}

__device__ __forceinline__ void ldsm2(uint32_t* r, uint32_t addr) {
    asm volatile("ldmatrix.sync.aligned.m8n8.x2.shared.b16 {%0,%1}, [%2];"
                 : "=r"(r[0]), "=r"(r[1]) : "r"(addr));
}

__device__ __forceinline__ void mma16816(float* c, const uint32_t* a, const uint32_t* b) {
    asm volatile(
        "mma.sync.aligned.m16n8k16.row.col.f32.f16.f16.f32 "
        "{%0,%1,%2,%3}, {%4,%5,%6,%7}, {%8,%9}, {%0,%1,%2,%3};"
        : "+f"(c[0]), "+f"(c[1]), "+f"(c[2]), "+f"(c[3])
        : "r"(a[0]), "r"(a[1]), "r"(a[2]), "r"(a[3]), "r"(b[0]), "r"(b[1]));
}

__device__ __forceinline__ void split_h(float x, __half& h, __half& l) {
    h = __float2half(x);
    l = __float2half(x - __half2float(h));
}

// ---------------- hi/lo fp16 split converters ----------------
__global__ void convert_w_kernel(const float* __restrict__ ew) {
    const size_t i = (size_t)blockIdx.x * blockDim.x + threadIdx.x;   // float4 index
    const float4 v = ((const float4*)ew)[i];
    float f[4] = {v.x, v.y, v.z, v.w};
    __half h[4], l[4];
#pragma unroll
    for (int j = 0; j < 4; j++) split_h(f[j], h[j], l[j]);
    *(uint2*)&g_wh[i * 4] = *(uint2*)h;
    if (i * 4 < (size_t)E * H * H)                  // lo only needed for layer 0
        *(uint2*)&g_wl[i * 4] = *(uint2*)l;
}

__global__ void convert_x_kernel(const float* __restrict__ X) {
    const size_t i = (size_t)blockIdx.x * blockDim.x + threadIdx.x;
    const float4 v = ((const float4*)X)[i];
    float f[4] = {v.x, v.y, v.z, v.w};
    __half h[4], l[4];
#pragma unroll
    for (int j = 0; j < 4; j++) split_h(f[j], h[j], l[j]);
    *(uint2*)&g_xh[i * 4] = *(uint2*)h;
    *(uint2*)&g_xl[i * 4] = *(uint2*)l;
}

// ---------------- gating: logits -> top2 -> softmax (fp32) + fused histogram ----------------
__global__ void gate_kernel(const float* __restrict__ X,
                            const float* __restrict__ gw,
                            const float* __restrict__ gb, int d) {
    __shared__ float xs[H];
    __shared__ float logit_sm[E];
    const int warp = threadIdx.x >> 5;
    const int lane = threadIdx.x & 31;
    const float* xin = (d == 0) ? X : g_x1;

    float w[32];
    const float* gwr = gw + (size_t)(d * E + warp) * H;
#pragma unroll
    for (int j = 0; j < 32; j++) w[j] = gwr[lane + 32 * j];
    const float bias = gb[d * E + warp];

    const int tok0 = blockIdx.x * 32;
    for (int tt = 0; tt < 32; tt++) {
        const int b = tok0 + tt;
        ((float2*)xs)[threadIdx.x] = ((const float2*)(xin + (size_t)b * H))[threadIdx.x];
        __syncthreads();
        float s = 0.f;
#pragma unroll
        for (int j = 0; j < 32; j++) s += w[j] * xs[lane + 32 * j];
#pragma unroll
        for (int o = 16; o; o >>= 1) s += __shfl_xor_sync(0xffffffffu, s, o);
        if (lane == 0) logit_sm[warp] = s + bias;
        __syncthreads();
        if (threadIdx.x == 0) {
            float v1 = -INFINITY; int i1 = 0;
#pragma unroll
            for (int e = 0; e < E; e++)
                if (logit_sm[e] > v1) { v1 = logit_sm[e]; i1 = e; }
            float v2 = -INFINITY; int i2 = 0;
#pragma unroll
            for (int e = 0; e < E; e++)
                if (e != i1 && logit_sm[e] > v2) { v2 = logit_sm[e]; i2 = e; }
            const float e2 = __expf(v2 - v1);
            const float inv = 1.f / (1.f + e2);
            g_idx[b * K + 0] = i1;  g_wgt[b * K + 0] = inv;
            g_idx[b * K + 1] = i2;  g_wgt[b * K + 1] = e2 * inv;
            atomicAdd(&g_counts[i1], 1);
            atomicAdd(&g_counts[i2], 1);
        }
        __syncthreads();
    }
}

// ---------------- bucketing ----------------
__global__ void zero_counts_kernel() {
    if (threadIdx.x < E) g_counts[threadIdx.x] = 0;
}

__global__ void scan_tiles_kernel() {
    if (threadIdx.x != 0) return;
    int off = 0;
    for (int e = 0; e < E; e++) {
        g_offs[e] = off;
        g_pos[e]  = off;
        off += g_counts[e];
    }
    g_offs[E] = off;
    int nt = 0;
    for (int e = 0; e < E; e++) {
        const int n = g_counts[e];
        for (int r = 0; r < n; r += TM) {
            g_tile_e[nt]    = e;
            g_tile_row[nt]  = g_offs[e] + r;
            g_tile_rows[nt] = (n - r < TM) ? (n - r) : TM;
            nt++;
        }
    }
    g_ntiles = nt;
}

__global__ void scatter_kernel() {
    int i = blockIdx.x * blockDim.x + threadIdx.x;
    if (i < B * K) {
        int e = g_idx[i];
        int p = atomicAdd(&g_pos[e], 1);
        g_perm[p] = i;
    }
}

// ---------------- fp16 multi-pass mma.sync grouped GEMM + fused epilogue ----------------
// PASSES==3 (layer 0): acc = Ah*Bh + Al*Bh + Ah*Bl   (residual ~3e-7)
// PASSES==2 (layer 1): acc = Ah*Bh + Al*Bh           (residual ~2e-4; no top-k downstream)
// 128x128 C tile, 8 warps in 2(m) x 4(n), warp tile 64x32, mma m16n8k16.
template <int PASSES>
__global__ __launch_bounds__(256, 1)
void expert_gemm_mma(const float* __restrict__ eb,
                     const float* __restrict__ pl,
                     const float* __restrict__ pr,
                     const float* __restrict__ pp,
                     const float* __restrict__ pb, int d)
{
    const int t = blockIdx.y;
    if (t >= g_ntiles) return;
    const int e    = g_tile_e[t];
    const int row0 = g_tile_row[t];
    const int rows = g_tile_rows[t];
    const int nb   = blockIdx.x * TN;
    const int de   = d * E + e;

    extern __shared__ char dsm[];
    const uint32_t sb = smem_u32(dsm);

    __shared__ int   toks_sm[TM];
    __shared__ int   slots_sm[TM];
    __shared__ float wgt_sm[TM];
    __shared__ float prm[5][TN];

    const int tid  = threadIdx.x;
    const int wid  = tid >> 5;
    const int lane = tid & 31;

    if (tid < TM) {
        int s = (tid < rows) ? g_perm[row0 + tid] : -1;
        slots_sm[tid] = s;
        toks_sm[tid]  = (s >= 0) ? (s >> 1) : -1;
        wgt_sm[tid]   = (s >= 0) ? g_wgt[s] : 0.f;
    }
    if (tid < TN) {
        const size_t pofs = (size_t)de * H + nb + tid;
        prm[0][tid] = eb[pofs];
        prm[1][tid] = pl[pofs];
        prm[2][tid] = pr[pofs];
        prm[3][tid] = pp[pofs];
        prm[4][tid] = pb[pofs];
    }
    __syncthreads();

    // loader geometry: q in [0,512): r=q>>2 (row), c=q&3 (16B chunk)
    const int r0l = tid >> 2,         c0l = tid & 3;
    const int r1l = (tid + 256) >> 2, c1l = c0l;
    const int tk0 = toks_sm[r0l], tk1 = toks_sm[r1l];
    const __half* Wh = g_wh + (size_t)de * H * H;
    const __half* Wl = g_wl + (size_t)e * H * H;   // valid only for d==0 (PASSES==3)

#define ISSUE_STAGE(i)                                                                   \
    do {                                                                                 \
        const int kb_ = (i) * TKB;                                                       \
        const uint32_t st_ = sb + ((i) & 1) * STAGE_B;                                   \
        /* A hi/lo */                                                                    \
        {                                                                                \
            const uint32_t o0 = st_ + r0l * ROWB + c0l * 16;                             \
            const uint32_t o1 = st_ + r1l * ROWB + c1l * 16;                             \
            const size_t g0 = (size_t)(tk0 < 0 ? 0 : tk0) * H + kb_ + c0l * 8;           \
            const size_t g1 = (size_t)(tk1 < 0 ? 0 : tk1) * H + kb_ + c1l * 8;           \
            cpasync16(o0,          g_xh + g0, tk0 < 0 ? 0 : 16);                         \
            cpasync16(o1,          g_xh + g1, tk1 < 0 ? 0 : 16);                         \
            cpasync16(o0 + TILE_B, g_xl + g0, tk0 < 0 ? 0 : 16);                         \
            cpasync16(o1 + TILE_B, g_xl + g1, tk1 < 0 ? 0 : 16);                         \
        }                                                                                \
        /* B hi (+lo for 3-pass) */                                                      \
        {                                                                                \
            const uint32_t o0 = st_ + 2 * TILE_B + r0l * ROWB + c0l * 16;                \
            const uint32_t o1 = st_ + 2 * TILE_B + r1l * ROWB + c1l * 16;                \
            const size_t g0 = (size_t)(nb + r0l) * H + kb_ + c0l * 8;                    \
            const size_t g1 = (size_t)(nb + r1l) * H + kb_ + c1l * 8;                    \
            cpasync16(o0,          Wh + g0, 16);                                         \
            cpasync16(o1,          Wh + g1, 16);                                         \
            if (PASSES == 3) {                                                           \
                cpasync16(o0 + TILE_B, Wl + g0, 16);                                     \
                cpasync16(o1 + TILE_B, Wl + g1, 16);                                     \
            }                                                                            \
        }                                                                                \
        asm volatile("cp.async.commit_group;" ::: "memory");                             \
    } while (0)

    float acc[4][4][4];
#pragma unroll
    for (int mi = 0; mi < 4; mi++)
#pragma unroll
        for (int ni = 0; ni < 4; ni++)
#pragma unroll
            for (int u = 0; u < 4; u++) acc[mi][ni][u] = 0.f;

    const int warp_m = wid & 1, warp_n = wid >> 1;
    const int m0 = warp_m * 64, n0 = warp_n * 32;

    const uint32_t a_off = (uint32_t)((m0 + (lane & 15)) * ROWB + (lane >> 4) * 16);
    const uint32_t b_off = (uint32_t)((n0 + (lane & 7)) * ROWB + ((lane >> 3) & 1) * 16);

    ISSUE_STAGE(0);
    ISSUE_STAGE(1);

    for (int i = 0; i < NC; i++) {
        if (i + 1 < NC) asm volatile("cp.async.wait_group 1;" ::: "memory");
        else            asm volatile("cp.async.wait_group 0;" ::: "memory");
        __syncthreads();

        const uint32_t st = sb + (i & 1) * STAGE_B;
        const uint32_t Ah = st + a_off;
        const uint32_t Al = Ah + TILE_B;
        const uint32_t Bh = st + 2 * TILE_B + b_off;
        const uint32_t Bl = Bh + TILE_B;

#pragma unroll
        for (int ks = 0; ks < 2; ks++) {
            uint32_t ah[4][4], al[4][4], bh[4][2], bl[4][2];
#pragma unroll
            for (int mi = 0; mi < 4; mi++) {
                ldsm4(ah[mi], Ah + mi * (16 * ROWB) + ks * 32);
                ldsm4(al[mi], Al + mi * (16 * ROWB) + ks * 32);
            }
#pragma unroll
            for (int ni = 0; ni < 4; ni++) {
                ldsm2(bh[ni], Bh + ni * (8 * ROWB) + ks * 32);
                if (PASSES == 3) ldsm2(bl[ni], Bl + ni * (8 * ROWB) + ks * 32);
            }
#pragma unroll
            for (int mi = 0; mi < 4; mi++)
#pragma unroll
                for (int ni = 0; ni < 4; ni++) {
                    mma16816(acc[mi][ni], ah[mi], bh[ni]);
                    mma16816(acc[mi][ni], al[mi], bh[ni]);
                    if (PASSES == 3) mma16816(acc[mi][ni], ah[mi], bl[ni]);
                }
        }
        __syncthreads();
        if (i + 2 < NC) ISSUE_STAGE(i + 2);
    }

    // ---------------- epilogue: bias + PReLU + gate weight ----------------
#pragma unroll
    for (int mi = 0; mi < 4; mi++) {
        const int ra  = m0 + mi * 16 + (lane >> 2);
        const int rb2 = ra + 8;
        const int sa = slots_sm[ra], sbt = slots_sm[rb2];
        const float wa = wgt_sm[ra], wb = wgt_sm[rb2];
#pragma unroll
        for (int ni = 0; ni < 4; ni++) {
            const int c = n0 + ni * 8 + (lane & 3) * 2;
            if (sa >= 0) {
                float2 o;
                float y0 = acc[mi][ni][0] + prm[0][c];
                float y1 = acc[mi][ni][1] + prm[0][c + 1];
                float d0 = y0 - prm[3][c],  d1 = y1 - prm[3][c + 1];
                o.x = (prm[4][c]   + (d0 >= 0.f ? d0 * prm[2][c]   : d0 * prm[1][c]))   * wa;
                o.y = (prm[4][c+1] + (d1 >= 0.f ? d1 * prm[2][c+1] : d1 * prm[1][c+1])) * wa;
                *(float2*)(g_ysel + (size_t)sa * H + nb + c) = o;
            }
            if (sbt >= 0) {
                float2 o;
                float y0 = acc[mi][ni][2] + prm[0][c];
                float y1 = acc[mi][ni][3] + prm[0][c + 1];
                float d0 = y0 - prm[3][c],  d1 = y1 - prm[3][c + 1];
                o.x = (prm[4][c]   + (d0 >= 0.f ? d0 * prm[2][c]   : d0 * prm[1][c]))   * wb;
                o.y = (prm[4][c+1] + (d1 >= 0.f ? d1 * prm[2][c+1] : d1 * prm[1][c+1])) * wb;
                *(float2*)(g_ysel + (size_t)sbt * H + nb + c) = o;
            }
        }
    }
#undef ISSUE_STAGE
}

// ---------------- combine the K=2 weighted slots (+fused fp16 split for layer 0) ----------------
__global__ void combine_kernel(float* __restrict__ out, int d) {
    const int i = blockIdx.x * blockDim.x + threadIdx.x;   // over B*H/4
    const int HQ = H / 4;
    const int b  = i / HQ;
    const int h4 = i - b * HQ;
    const float4* y = (const float4*)g_ysel;
    float4 a = y[(size_t)(2 * b) * HQ + h4];
    float4 c = y[(size_t)(2 * b + 1) * HQ + h4];
    float4 r = make_float4(a.x + c.x, a.y + c.y, a.z + c.z, a.w + c.w);
    if (d == 0) {
        ((float4*)g_x1)[i] = r;
        float f[4] = {r.x, r.y, r.z, r.w};
        __half h[4], l[4];
#pragma unroll
        for (int j = 0; j < 4; j++) split_h(f[j], h[j], l[j]);
        *(uint2*)&g_xh[(size_t)i * 4] = *(uint2*)h;
        *(uint2*)&g_xl[(size_t)i * 4] = *(uint2*)l;
    } else {
        ((float4*)out)[i] = r;
    }
}

// ---------------- launch ----------------
extern "C" void kernel_launch(void* const* d_in, const int* in_sizes, int n_in,
                              void* d_out, int out_size) {
    const float* X  = (const float*)d_in[0];
    const float* gw = (const float*)d_in[1];
    const float* gb = (const float*)d_in[2];
    const float* ew = (const float*)d_in[3];
    const float* eb = (const float*)d_in[4];
    const float* pl = (const float*)d_in[5];
    const float* pr = (const float*)d_in[6];
    const float* pp = (const float*)d_in[7];
    const float* pb = (const float*)d_in[8];
    float* out = (float*)d_out;

    static bool attr_done = false;
    if (!attr_done) {
        cudaFuncSetAttribute(expert_gemm_mma<3>,
                             cudaFuncAttributeMaxDynamicSharedMemorySize, DYN_SMEM);
        cudaFuncSetAttribute(expert_gemm_mma<2>,
                             cudaFuncAttributeMaxDynamicSharedMemorySize, DYN_SMEM);
        attr_done = true;
    }

    // once per launch: weights -> fp16 hi/lo, X -> fp16 hi/lo
    convert_w_kernel<<<(int)((size_t)D * E * H * H / 4 / 256), 256>>>(ew);
    convert_x_kernel<<<B * H / 4 / 256, 256>>>(X);

    for (int d = 0; d < D; d++) {
        zero_counts_kernel<<<1, 32>>>();
        gate_kernel<<<B / 32, 512>>>(X, gw, gb, d);
        scan_tiles_kernel<<<1, 32>>>();
        scatter_kernel<<<(B * K + 255) / 256, 256>>>();
        if (d == 0)
            expert_gemm_mma<3><<<dim3(H / TN, MAXT), 256, DYN_SMEM>>>(eb, pl, pr, pp, pb, d);
        else
            expert_gemm_mma<2><<<dim3(H / TN, MAXT), 256, DYN_SMEM>>>(eb, pl, pr, pp, pb, d);
        combine_kernel<<<(B * H / 4 + 255) / 256, 256>>>(out, d);
    }
}